// round 3
// baseline (speedup 1.0000x reference)
#include <cuda_runtime.h>
#include <cuda_bf16.h>
#include <cstddef>

// SAPA pipeline, fp32 + packed f32x2 FMA, occupancy-oriented layout.
// Shapes: B=4, C=256, E=32, lo 64x64, hi 128x128, K=5 (pad 2), GROUPS=32.

#define B_      4
#define C_      256
#define E_      32
#define NPIX_LO 4096
#define NPIX_HI 16384
#define EPSF    1e-5f

typedef unsigned long long ull;

#define FMA2(d, a, b, c) \
    asm("fma.rn.f32x2 %0, %1, %2, %3;" : "=l"(d) : "l"(a), "l"(b), "l"(c))

__device__ __forceinline__ ull pack2(float lo, float hi) {
    ull r; asm("mov.b64 %0, {%1, %2};" : "=l"(r) : "f"(lo), "f"(hi)); return r;
}
__device__ __forceinline__ ull dup2(float v) { return pack2(v, v); }
__device__ __forceinline__ void unpack2(float& lo, float& hi, ull d) {
    asm("mov.b64 {%0, %1}, %2;" : "=f"(lo), "=f"(hi) : "l"(d));
}

// ---------------- device scratch ----------------
__device__ float  g_ps[640];
__device__ float  g_pss[640];
__device__ float2 g_st_y[B_ * C_];              // (scale, shift) per (b,c) for y
__device__ float2 g_st_x[B_ * C_];              // for x
__device__ float  g_qwT[C_ * E_];               // q_w transposed [c][e]
__device__ float  g_kwT[C_ * E_];               // k_w transposed [c][e]
__device__ float  g_q[B_ * NPIX_HI * E_];       // q  [b][pix_hi][e]
__device__ float  g_k[B_ * NPIX_LO * E_];       // k  [b][pix_lo][e]
__device__ float  g_attn[B_ * 25 * NPIX_HI];    // attn [b][o][pix_hi]

// ============================================================
// Kernel 1: partial sums for GN stats. 640 blocks x 256.
// blocks [0,512): y in 32768-float chunks; [512,640): x groups.
// ============================================================
__global__ void __launch_bounds__(256)
stats_partial_kernel(const float* __restrict__ y, const float* __restrict__ x)
{
    int bid = blockIdx.x, tid = threadIdx.x;
    const float4* p = (bid < 512)
        ? (const float4*)y + (size_t)bid * 8192
        : (const float4*)x + (size_t)(bid - 512) * 8192;

    float s = 0.f, ss = 0.f;
#pragma unroll 4
    for (int i = tid; i < 8192; i += 256) {
        float4 v = p[i];
        s  += (v.x + v.y) + (v.z + v.w);
        ss += (v.x*v.x + v.y*v.y) + (v.z*v.z + v.w*v.w);
    }
#pragma unroll
    for (int off = 16; off > 0; off >>= 1) {
        s  += __shfl_xor_sync(0xffffffffu, s,  off);
        ss += __shfl_xor_sync(0xffffffffu, ss, off);
    }
    __shared__ float ws[8], wss[8];
    if ((tid & 31) == 0) { ws[tid >> 5] = s; wss[tid >> 5] = ss; }
    __syncthreads();
    if (tid == 0) {
        float ts = 0.f, tss = 0.f;
#pragma unroll
        for (int w = 0; w < 8; w++) { ts += ws[w]; tss += wss[w]; }
        g_ps[bid] = ts; g_pss[bid] = tss;
    }
}

// ============================================================
// Kernel 2: finalize stats -> (scale,shift) tables; transpose weights.
// grid 33 x 256.  block 0: stats+tables; blocks 1..32: transpose.
// ============================================================
__global__ void __launch_bounds__(256)
finalize_kernel(const float* __restrict__ qw, const float* __restrict__ kw,
                const float* __restrict__ gyw, const float* __restrict__ gyb,
                const float* __restrict__ gxw, const float* __restrict__ gxb)
{
    int tid = threadIdx.x;
    if (blockIdx.x == 0) {
        __shared__ float mu_s[256], rs_s[256];
        {
            float s, ss, n;
            if (tid < 128) {
                s  = (g_ps[4*tid]  + g_ps[4*tid+1])  + (g_ps[4*tid+2]  + g_ps[4*tid+3]);
                ss = (g_pss[4*tid] + g_pss[4*tid+1]) + (g_pss[4*tid+2] + g_pss[4*tid+3]);
                n = 131072.f;
            } else {
                int g = tid - 128;
                s = g_ps[512 + g]; ss = g_pss[512 + g]; n = 32768.f;
            }
            float mu  = s / n;
            float var = ss / n - mu * mu;
            mu_s[tid] = mu; rs_s[tid] = rsqrtf(var + EPSF);
        }
        __syncthreads();
        for (int i = tid; i < 1024; i += 256) {
            int b = i >> 8, c = i & 255, g = c >> 3;
            {
                float mu = mu_s[b*32 + g], r = rs_s[b*32 + g];
                float sc = r * gyw[c];
                g_st_y[i] = make_float2(sc, gyb[c] - mu * sc);
            }
            {
                float mu = mu_s[128 + b*32 + g], r = rs_s[128 + b*32 + g];
                float sc = r * gxw[c];
                g_st_x[i] = make_float2(sc, gxb[c] - mu * sc);
            }
        }
    } else {
        int i = (blockIdx.x - 1) * 256 + tid;
        int c = i >> 5, e = i & 31;
        g_qwT[i] = qw[e * C_ + c];
        g_kwT[i] = kw[e * C_ + c];
    }
}

// ============================================================
// Kernel 3: unified projection (q and k), GN folded.
// grid 1280 x 128.  blocks [0,1024): q over y; [1024,1280): k over x.
// thread = (pixel-pair p = tid&31, e-slice eh = tid>>5 of 8 e's).
// Weight LDS are warp-uniform broadcasts (eh constant per warp).
// ============================================================
__global__ void __launch_bounds__(128)
proj_kernel(const float* __restrict__ y, const float* __restrict__ x,
            const float* __restrict__ q_b, const float* __restrict__ k_b)
{
    __shared__ float  w_s[C_ * E_];
    __shared__ float2 st_s[C_];

    int tid = threadIdx.x;
    int blk = blockIdx.x;
    const float* inp; const float* wsrc; const float2* stsrc; const float* bias;
    float* outp; int npix, pixbase;
    if (blk < 1024) {
        int b = blk >> 8; pixbase = (blk & 255) * 64;
        inp = y + (size_t)b * C_ * NPIX_HI; npix = NPIX_HI;
        wsrc = g_qwT; stsrc = g_st_y + b * C_; bias = q_b;
        outp = g_q + (size_t)b * NPIX_HI * E_;
    } else {
        int bk = blk - 1024;
        int b = bk >> 6; pixbase = (bk & 63) * 64;
        inp = x + (size_t)b * C_ * NPIX_LO; npix = NPIX_LO;
        wsrc = g_kwT; stsrc = g_st_x + b * C_; bias = k_b;
        outp = g_k + (size_t)b * NPIX_LO * E_;
    }

    for (int i = tid; i < (C_ * E_) / 4; i += 128)
        ((float4*)w_s)[i] = ((const float4*)wsrc)[i];
    for (int i = tid; i < C_; i += 128) st_s[i] = stsrc[i];
    __syncthreads();

    int p  = tid & 31;
    int eh = tid >> 5;
    int pix0 = pixbase + 2 * p;
    const ulonglong2* w22 = (const ulonglong2*)w_s;

    ull a0[4], a1[4];
#pragma unroll
    for (int j = 0; j < 4; j++) {
        ull bv = pack2(__ldg(&bias[eh*8 + 2*j]), __ldg(&bias[eh*8 + 2*j + 1]));
        a0[j] = bv; a1[j] = bv;
    }

    const float* ip = inp + pix0;
#pragma unroll 4
    for (int c = 0; c < C_; c++) {
        float2 st = st_s[c];
        float2 yv = *(const float2*)(ip + (size_t)c * npix);
        ull u0 = dup2(fmaf(yv.x, st.x, st.y));
        ull u1 = dup2(fmaf(yv.y, st.x, st.y));
        ulonglong2 wa = w22[c*8 + eh*2];
        ulonglong2 wb = w22[c*8 + eh*2 + 1];
        FMA2(a0[0], wa.x, u0, a0[0]); FMA2(a0[1], wa.y, u0, a0[1]);
        FMA2(a0[2], wb.x, u0, a0[2]); FMA2(a0[3], wb.y, u0, a0[3]);
        FMA2(a1[0], wa.x, u1, a1[0]); FMA2(a1[1], wa.y, u1, a1[1]);
        FMA2(a1[2], wb.x, u1, a1[2]); FMA2(a1[3], wb.y, u1, a1[3]);
    }

    ulonglong2* o0 = (ulonglong2*)(outp + (size_t)pix0 * E_ + eh * 8);
    o0[0] = make_ulonglong2(a0[0], a0[1]);
    o0[1] = make_ulonglong2(a0[2], a0[3]);
    ulonglong2* o1 = (ulonglong2*)(outp + (size_t)(pix0 + 1) * E_ + eh * 8);
    o1[0] = make_ulonglong2(a1[0], a1[1]);
    o1[1] = make_ulonglong2(a1[2], a1[3]);
}

// ============================================================
// Kernel 4: logits + softmax -> g_attn.
// grid (8, 16, 4) x 128.  lo tile 4x8 (hi 8x16), thread = 1 hi pixel.
// k halo tile 8x12 points x 32e in smem (12 KB), [point][e] layout.
// ============================================================
__global__ void __launch_bounds__(128)
attn_kernel()
{
    __shared__ float k_s[96 * E_];

    int tid = threadIdx.x;
    int b   = blockIdx.z;
    int th0 = blockIdx.y * 4;
    int tw0 = blockIdx.x * 8;

    const float4* ksrc = (const float4*)g_k;
    for (int i = tid; i < 96 * 8; i += 128) {
        int pt = i >> 3, c4 = i & 7;
        int jy = pt / 12, jx = pt - jy * 12;
        int gy = th0 - 2 + jy, gx = tw0 - 2 + jx;
        float4 v = make_float4(0.f, 0.f, 0.f, 0.f);
        if (gy >= 0 && gy < 64 && gx >= 0 && gx < 64)
            v = ksrc[((size_t)(b * NPIX_LO + (gy << 6) + gx) << 3) + c4];
        ((float4*)k_s)[(pt << 3) + c4] = v;
    }
    __syncthreads();

    int oy = tid >> 4, ox = tid & 15;
    int gy2 = th0 * 2 + oy, gx2 = tw0 * 2 + ox;
    int po = (gy2 << 7) + gx2;

    ull qa[16];
    const ulonglong2* qp = (const ulonglong2*)(g_q + ((size_t)b * NPIX_HI + po) * E_);
#pragma unroll
    for (int j = 0; j < 8; j++) { ulonglong2 v = qp[j]; qa[2*j] = v.x; qa[2*j+1] = v.y; }

    int lh0 = oy >> 1, lw0 = ox >> 1;
    float att[25];
    float mx = -1e30f;
#pragma unroll
    for (int o = 0; o < 25; o++) {
        int dy = o / 5, dx = o - 5 * dy;
        const ulonglong2* kp = (const ulonglong2*)&k_s[((lh0 + dy) * 12 + lw0 + dx) * E_];
        ull s0 = 0ull, s1 = 0ull, s2 = 0ull, s3 = 0ull;
#pragma unroll
        for (int j = 0; j < 4; j++) {
            ulonglong2 va = kp[2*j], vb = kp[2*j + 1];
            FMA2(s0, qa[4*j],     va.x, s0);
            FMA2(s1, qa[4*j + 1], va.y, s1);
            FMA2(s2, qa[4*j + 2], vb.x, s2);
            FMA2(s3, qa[4*j + 3], vb.y, s3);
        }
        float f0,f1,f2,f3,f4,f5,f6,f7;
        unpack2(f0, f1, s0); unpack2(f2, f3, s1);
        unpack2(f4, f5, s2); unpack2(f6, f7, s3);
        float lg = ((f0+f1) + (f2+f3)) + ((f4+f5) + (f6+f7));
        att[o] = lg;
        mx = fmaxf(mx, lg);
    }

    float den = 0.f;
#pragma unroll
    for (int o = 0; o < 25; o++) { float pz = __expf(att[o] - mx); att[o] = pz; den += pz; }
    float inv = 1.f / den;
#pragma unroll
    for (int o = 0; o < 25; o++)
        g_attn[((size_t)(b * 25 + o) << 14) + po] = att[o] * inv;
}

// ============================================================
// Kernel 5: aggregation.  grid (64, 8, 4) x 128.
// lo tile 8x8 (hi 16x16); thread = 2 horizontally-adjacent hi pixels
// (same lo tap -> x LDS reused for both). 32 channels per block.
// ============================================================
__global__ void __launch_bounds__(128)
agg_kernel(const float* __restrict__ x, float* __restrict__ out)
{
    __shared__ float x_s[144 * 8];

    int tid = threadIdx.x;
    int b   = blockIdx.z;
    int th0 = (blockIdx.x >> 3) * 8;
    int tw0 = (blockIdx.x & 7) * 8;
    int cb  = blockIdx.y * 32;

    int oy = tid >> 3, oxp = tid & 7;
    int gy2 = th0 * 2 + oy, gx2 = tw0 * 2 + oxp * 2;
    int po  = (gy2 << 7) + gx2;
    int lh = oy >> 1, lw = oxp;

    float att0[25], att1[25];
#pragma unroll
    for (int o = 0; o < 25; o++) {
        float2 a = *(const float2*)&g_attn[((size_t)(b * 25 + o) << 14) + po];
        att0[o] = a.x; att1[o] = a.y;
    }

    const float* xb = x + (size_t)b * C_ * NPIX_LO;
    float* ob = out + (size_t)b * C_ * NPIX_HI + po;

    for (int cg = 0; cg < 4; cg++) {
        int c0 = cb + cg * 8;
        __syncthreads();
        for (int i = tid; i < 1152; i += 128) {
            int ch = i / 144, pt = i - ch * 144;
            int jy = pt / 12, jx = pt - jy * 12;
            int gy = th0 - 2 + jy, gx = tw0 - 2 + jx;
            float v = 0.f;
            if (gy >= 0 && gy < 64 && gx >= 0 && gx < 64)
                v = xb[(size_t)(c0 + ch) * NPIX_LO + (gy << 6) + gx];
            x_s[pt * 8 + ch] = v;
        }
        __syncthreads();

        ull a0[4], a1[4];
#pragma unroll
        for (int j = 0; j < 4; j++) { a0[j] = 0ull; a1[j] = 0ull; }
#pragma unroll
        for (int o = 0; o < 25; o++) {
            int dy = o / 5, dx = o - 5 * dy;
            const ulonglong2* xp = (const ulonglong2*)&x_s[((lh + dy) * 12 + lw + dx) * 8];
            ulonglong2 v0 = xp[0], v1 = xp[1];
            ull w0 = dup2(att0[o]), w1 = dup2(att1[o]);
            FMA2(a0[0], w0, v0.x, a0[0]); FMA2(a0[1], w0, v0.y, a0[1]);
            FMA2(a0[2], w0, v1.x, a0[2]); FMA2(a0[3], w0, v1.y, a0[3]);
            FMA2(a1[0], w1, v0.x, a1[0]); FMA2(a1[1], w1, v0.y, a1[1]);
            FMA2(a1[2], w1, v1.x, a1[2]); FMA2(a1[3], w1, v1.y, a1[3]);
        }
#pragma unroll
        for (int j = 0; j < 4; j++) {
            float l0, h0, l1, h1;
            unpack2(l0, h0, a0[j]);
            unpack2(l1, h1, a1[j]);
            *(ull*)&ob[(size_t)(c0 + 2*j)     * NPIX_HI] = pack2(l0, l1);
            *(ull*)&ob[(size_t)(c0 + 2*j + 1) * NPIX_HI] = pack2(h0, h1);
        }
    }
}

// ============================================================
extern "C" void kernel_launch(void* const* d_in, const int* in_sizes, int n_in,
                              void* d_out, int out_size)
{
    (void)in_sizes; (void)n_in; (void)out_size;
    const float* y      = (const float*)d_in[0];
    const float* x      = (const float*)d_in[1];
    const float* gn_y_w = (const float*)d_in[2];
    const float* gn_y_b = (const float*)d_in[3];
    const float* gn_x_w = (const float*)d_in[4];
    const float* gn_x_b = (const float*)d_in[5];
    const float* q_w    = (const float*)d_in[6];
    const float* q_b    = (const float*)d_in[7];
    const float* k_w    = (const float*)d_in[8];
    const float* k_b    = (const float*)d_in[9];
    float* out = (float*)d_out;

    stats_partial_kernel<<<640, 256>>>(y, x);
    finalize_kernel<<<33, 256>>>(q_w, k_w, gn_y_w, gn_y_b, gn_x_w, gn_x_b);
    proj_kernel<<<1280, 128>>>(y, x, q_b, k_b);
    attn_kernel<<<dim3(8, 16, 4), 128>>>();
    agg_kernel<<<dim3(64, 8, 4), 128>>>(x, out);
}

// round 4
// speedup vs baseline: 1.3019x; 1.3019x over previous
#include <cuda_runtime.h>
#include <cuda_bf16.h>
#include <cstddef>

// SAPA pipeline R4: R2 base + 2-way C-split attention + 8-slice kproj.
#define B_      4
#define C_      256
#define E_      32
#define NPIX_LO 4096
#define NPIX_HI 16384
#define TL      8
#define HALO    12
#define KSTRIDE 36
#define EPSF    1e-5f

typedef unsigned long long ull;

#define FMA2(d, a, b, c) \
    asm("fma.rn.f32x2 %0, %1, %2, %3;" : "=l"(d) : "l"(a), "l"(b), "l"(c))

__device__ __forceinline__ ull pack2(float lo, float hi) {
    ull r; asm("mov.b64 %0, {%1, %2};" : "=l"(r) : "f"(lo), "f"(hi)); return r;
}
__device__ __forceinline__ ull dup2(float v) { return pack2(v, v); }
__device__ __forceinline__ void unpack2(float& lo, float& hi, ull d) {
    asm("mov.b64 {%0, %1}, %2;" : "=f"(lo), "=f"(hi) : "l"(d));
}

// ---------------- device scratch ----------------
__device__ float  g_ps[640];
__device__ float  g_pss[640];
__device__ float2 g_st_y[B_ * C_];
__device__ float2 g_st_x[B_ * C_];
__device__ float  g_qwT[C_ * E_];                 // [c][e]
__device__ float  g_kwT[C_ * E_];                 // [c][e]
__device__ float  g_k[B_ * E_ * NPIX_LO];         // [b][e][pix_lo]
__device__ float  g_logits[2 * B_ * 25 * NPIX_HI]; // [half][b][o][pix_hi]
__device__ float  g_attn[B_ * 25 * NPIX_HI];      // [b][o][pix_hi]

// ============================================================
// Kernel 1: partial sums. blocks [0,512): y chunks; [512,640): x groups.
// ============================================================
__global__ void __launch_bounds__(256)
stats_partial_kernel(const float* __restrict__ y, const float* __restrict__ x)
{
    int bid = blockIdx.x, tid = threadIdx.x;
    const float4* p = (bid < 512)
        ? (const float4*)y + (size_t)bid * 8192
        : (const float4*)x + (size_t)(bid - 512) * 8192;

    float s = 0.f, ss = 0.f;
#pragma unroll 4
    for (int i = tid; i < 8192; i += 256) {
        float4 v = p[i];
        s  += (v.x + v.y) + (v.z + v.w);
        ss += (v.x*v.x + v.y*v.y) + (v.z*v.z + v.w*v.w);
    }
#pragma unroll
    for (int off = 16; off > 0; off >>= 1) {
        s  += __shfl_xor_sync(0xffffffffu, s,  off);
        ss += __shfl_xor_sync(0xffffffffu, ss, off);
    }
    __shared__ float ws[8], wss[8];
    if ((tid & 31) == 0) { ws[tid >> 5] = s; wss[tid >> 5] = ss; }
    __syncthreads();
    if (tid == 0) {
        float ts = 0.f, tss = 0.f;
#pragma unroll
        for (int w = 0; w < 8; w++) { ts += ws[w]; tss += wss[w]; }
        g_ps[bid] = ts; g_pss[bid] = tss;
    }
}

// ============================================================
// Kernel 2: finalize stats -> (scale,shift) tables; transpose weights.
// ============================================================
__global__ void __launch_bounds__(256)
finalize_kernel(const float* __restrict__ qw, const float* __restrict__ kw,
                const float* __restrict__ gyw, const float* __restrict__ gyb,
                const float* __restrict__ gxw, const float* __restrict__ gxb)
{
    int tid = threadIdx.x;
    if (blockIdx.x == 0) {
        __shared__ float mu_s[256], rs_s[256];
        {
            float s, ss, n;
            if (tid < 128) {
                s  = (g_ps[4*tid]  + g_ps[4*tid+1])  + (g_ps[4*tid+2]  + g_ps[4*tid+3]);
                ss = (g_pss[4*tid] + g_pss[4*tid+1]) + (g_pss[4*tid+2] + g_pss[4*tid+3]);
                n = 131072.f;
            } else {
                int g = tid - 128;
                s = g_ps[512 + g]; ss = g_pss[512 + g]; n = 32768.f;
            }
            float mu  = s / n;
            float var = ss / n - mu * mu;
            mu_s[tid] = mu; rs_s[tid] = rsqrtf(var + EPSF);
        }
        __syncthreads();
        for (int i = tid; i < 1024; i += 256) {
            int b = i >> 8, c = i & 255, g = c >> 3;
            {
                float mu = mu_s[b*32 + g], r = rs_s[b*32 + g];
                float sc = r * gyw[c];
                g_st_y[i] = make_float2(sc, gyb[c] - mu * sc);
            }
            {
                float mu = mu_s[128 + b*32 + g], r = rs_s[128 + b*32 + g];
                float sc = r * gxw[c];
                g_st_x[i] = make_float2(sc, gxb[c] - mu * sc);
            }
        }
    } else {
        int i = (blockIdx.x - 1) * 256 + tid;
        int c = i >> 5, e = i & 31;
        g_qwT[i] = qw[e * C_ + c];
        g_kwT[i] = kw[e * C_ + c];
    }
}

// ============================================================
// Kernel 3: k projection. grid (128, 4) x 256.
// Block = 32 pixels x 8 c-slices (32 c each); smem reduce.
// ============================================================
__global__ void __launch_bounds__(256)
kproj_kernel(const float* __restrict__ x, const float* __restrict__ k_b)
{
    __shared__ float sm[8448 + 512];
    float* w_s = sm;            // 8192 used (reused as r_s)
    float* r_s = sm;            // 256*33 = 8448
    float* s_s = sm + 8448;
    float* t_s = sm + 8704;

    int tid = threadIdx.x;
    int b   = blockIdx.y;
    int p   = tid & 31;
    int pix = blockIdx.x * 32 + p;

    for (int i = tid; i < (C_ * E_) / 4; i += 256)
        ((float4*)w_s)[i] = ((const float4*)g_kwT)[i];
    {
        float2 st = g_st_x[b * C_ + tid];
        s_s[tid] = st.x; t_s[tid] = st.y;
    }
    __syncthreads();

    const float* xp = x + (size_t)b * C_ * NPIX_LO + pix;
    const ulonglong2* w2 = (const ulonglong2*)w_s;
    const float4* s4 = (const float4*)s_s;
    const float4* t4 = (const float4*)t_s;

    ull qa2[16];
#pragma unroll
    for (int j = 0; j < 16; j++) qa2[j] = 0ull;

    int cbase = (tid >> 5) * 32;
#pragma unroll 2
    for (int c0 = cbase; c0 < cbase + 32; c0 += 4) {
        float xv0 = xp[(size_t)(c0 + 0) * NPIX_LO];
        float xv1 = xp[(size_t)(c0 + 1) * NPIX_LO];
        float xv2 = xp[(size_t)(c0 + 2) * NPIX_LO];
        float xv3 = xp[(size_t)(c0 + 3) * NPIX_LO];
        float4 sc = s4[c0 >> 2], tc = t4[c0 >> 2];
        ull u0 = dup2(fmaf(xv0, sc.x, tc.x));
        ull u1 = dup2(fmaf(xv1, sc.y, tc.y));
        ull u2 = dup2(fmaf(xv2, sc.z, tc.z));
        ull u3 = dup2(fmaf(xv3, sc.w, tc.w));
#pragma unroll
        for (int j = 0; j < 8; j++) {
            ulonglong2 w0 = w2[(c0 + 0) * 8 + j];
            FMA2(qa2[2*j],   w0.x, u0, qa2[2*j]);
            FMA2(qa2[2*j+1], w0.y, u0, qa2[2*j+1]);
            ulonglong2 w1 = w2[(c0 + 1) * 8 + j];
            FMA2(qa2[2*j],   w1.x, u1, qa2[2*j]);
            FMA2(qa2[2*j+1], w1.y, u1, qa2[2*j+1]);
            ulonglong2 wv = w2[(c0 + 2) * 8 + j];
            FMA2(qa2[2*j],   wv.x, u2, qa2[2*j]);
            FMA2(qa2[2*j+1], wv.y, u2, qa2[2*j+1]);
            ulonglong2 w3 = w2[(c0 + 3) * 8 + j];
            FMA2(qa2[2*j],   w3.x, u3, qa2[2*j]);
            FMA2(qa2[2*j+1], w3.y, u3, qa2[2*j+1]);
        }
    }

    __syncthreads();
#pragma unroll
    for (int j = 0; j < 16; j++) {
        float lo, hi; unpack2(lo, hi, qa2[j]);
        r_s[tid * 33 + 2*j]     = lo;
        r_s[tid * 33 + 2*j + 1] = hi;
    }
    __syncthreads();

    int q4 = tid >> 5;                 // e-quad 0..7
    int p2 = tid & 31;
    float acc[4];
#pragma unroll
    for (int j = 0; j < 4; j++) acc[j] = __ldg(&k_b[q4 * 4 + j]);
#pragma unroll
    for (int s = 0; s < 8; s++) {
        const float* rp = &r_s[(s * 32 + p2) * 33 + q4 * 4];
#pragma unroll
        for (int j = 0; j < 4; j++) acc[j] += rp[j];
    }
    int pix2 = blockIdx.x * 32 + p2;
#pragma unroll
    for (int j = 0; j < 4; j++)
        g_k[((size_t)(b * E_ + q4 * 4 + j) << 12) + pix2] = acc[j];
}

// ============================================================
// Kernel 4: partial q-proj (c-half) + partial logits -> g_logits.
// grid (8, 8, 8): z = b*2 + half.  block 256 = 16x16 hi tile.
// ============================================================
__global__ void __launch_bounds__(256)
attn_partial_kernel(const float* __restrict__ y, const float* __restrict__ q_b)
{
    __shared__ float w_s[128 * E_];        // half of q_w, [cl][e]
    __shared__ float sy_s[128], ty_s[128];
    __shared__ float k_s[HALO * HALO * KSTRIDE];

    int tid  = threadIdx.x;
    int b    = blockIdx.z >> 1;
    int half = blockIdx.z & 1;
    int th0  = blockIdx.y * TL;
    int tw0  = blockIdx.x * TL;

    for (int i = tid; i < (128 * E_) / 4; i += 256)
        ((float4*)w_s)[i] = ((const float4*)g_qwT)[half * 1024 + i];
    if (tid < 128) {
        float2 st = g_st_y[b * C_ + half * 128 + tid];
        sy_s[tid] = st.x; ty_s[tid] = st.y;
    }
    for (int i = tid; i < E_ * HALO * HALO; i += 256) {
        int e  = i / (HALO * HALO);
        int j  = i - e * (HALO * HALO);
        int jy = j / HALO, jx = j - jy * HALO;
        int gy = th0 - 2 + jy, gx = tw0 - 2 + jx;
        float v = 0.f;
        if (gy >= 0 && gy < 64 && gx >= 0 && gx < 64)
            v = g_k[((size_t)(b * E_ + e) << 12) + (gy << 6) + gx];
        k_s[j * KSTRIDE + e] = v;
    }
    __syncthreads();

    int oy  = tid >> 4, ox = tid & 15;
    int gy2 = th0 * 2 + oy, gx2 = tw0 * 2 + ox;
    const float* yp = y + ((size_t)b * C_ + half * 128) * NPIX_HI + (gy2 << 7) + gx2;
    const ulonglong2* w2 = (const ulonglong2*)w_s;
    const float4* sy4 = (const float4*)sy_s;
    const float4* ty4 = (const float4*)ty_s;

    ull qa2[16];
#pragma unroll
    for (int j = 0; j < 16; j++)
        qa2[j] = half ? 0ull : pack2(__ldg(&q_b[2*j]), __ldg(&q_b[2*j + 1]));

#pragma unroll 2
    for (int c0 = 0; c0 < 128; c0 += 4) {
        float yv0 = yp[(size_t)(c0 + 0) * NPIX_HI];
        float yv1 = yp[(size_t)(c0 + 1) * NPIX_HI];
        float yv2 = yp[(size_t)(c0 + 2) * NPIX_HI];
        float yv3 = yp[(size_t)(c0 + 3) * NPIX_HI];
        float4 sc = sy4[c0 >> 2], tc = ty4[c0 >> 2];
        ull u0 = dup2(fmaf(yv0, sc.x, tc.x));
        ull u1 = dup2(fmaf(yv1, sc.y, tc.y));
        ull u2 = dup2(fmaf(yv2, sc.z, tc.z));
        ull u3 = dup2(fmaf(yv3, sc.w, tc.w));
#pragma unroll
        for (int j = 0; j < 8; j++) {
            ulonglong2 w0 = w2[(c0 + 0) * 8 + j];
            FMA2(qa2[2*j],   w0.x, u0, qa2[2*j]);
            FMA2(qa2[2*j+1], w0.y, u0, qa2[2*j+1]);
            ulonglong2 w1 = w2[(c0 + 1) * 8 + j];
            FMA2(qa2[2*j],   w1.x, u1, qa2[2*j]);
            FMA2(qa2[2*j+1], w1.y, u1, qa2[2*j+1]);
            ulonglong2 wv = w2[(c0 + 2) * 8 + j];
            FMA2(qa2[2*j],   wv.x, u2, qa2[2*j]);
            FMA2(qa2[2*j+1], wv.y, u2, qa2[2*j+1]);
            ulonglong2 w3 = w2[(c0 + 3) * 8 + j];
            FMA2(qa2[2*j],   w3.x, u3, qa2[2*j]);
            FMA2(qa2[2*j+1], w3.y, u3, qa2[2*j+1]);
        }
    }

    // partial logits vs shared k tile
    int lh = oy >> 1, lw = ox >> 1;
    int pixhi = (gy2 << 7) + gx2;
    float* lg_out = g_logits + ((size_t)((half * B_ + b) * 25) << 14) + pixhi;
#pragma unroll
    for (int o = 0; o < 25; o++) {
        int dy = o / 5, dx = o - 5 * dy;
        const ulonglong2* kp = (const ulonglong2*)
            &k_s[((lh + dy) * HALO + (lw + dx)) * KSTRIDE];
        ull sa = 0ull, sb = 0ull;
#pragma unroll
        for (int j = 0; j < 8; j++) {
            ulonglong2 kv = kp[j];
            FMA2(sa, qa2[2*j],   kv.x, sa);
            FMA2(sb, qa2[2*j+1], kv.y, sb);
        }
        float a0, a1, b0, b1;
        unpack2(a0, a1, sa); unpack2(b0, b1, sb);
        lg_out[(size_t)o << 14] = (a0 + a1) + (b0 + b1);
    }
}

// ============================================================
// Kernel 5: sum halves + softmax -> g_attn.  grid 512 x 128.
// ============================================================
__global__ void __launch_bounds__(128)
softmax_kernel()
{
    int i = blockIdx.x * 128 + threadIdx.x;    // 0 .. 65535
    int b = i >> 14, pix = i & 16383;
    const float* l0 = g_logits + ((size_t)(b * 25) << 14) + pix;
    const float* l1 = g_logits + ((size_t)((B_ + b) * 25) << 14) + pix;

    float att[25];
    float mx = -1e30f;
#pragma unroll
    for (int o = 0; o < 25; o++) {
        float v = l0[(size_t)o << 14] + l1[(size_t)o << 14];
        att[o] = v;
        mx = fmaxf(mx, v);
    }
    float den = 0.f;
#pragma unroll
    for (int o = 0; o < 25; o++) { float p = __expf(att[o] - mx); att[o] = p; den += p; }
    float inv = 1.f / den;
    float* ap = g_attn + ((size_t)(b * 25) << 14) + pix;
#pragma unroll
    for (int o = 0; o < 25; o++) ap[(size_t)o << 14] = att[o] * inv;
}

// ============================================================
// Kernel 6: aggregation (R2 verbatim). grid (64, 8, 4) x 256.
// ============================================================
__global__ void __launch_bounds__(256)
sapa_agg_kernel(const float* __restrict__ x, float* __restrict__ out)
{
    __shared__ float x_s[HALO * HALO * 12];

    int tid = threadIdx.x;
    int b   = blockIdx.z;
    int th0 = (blockIdx.x >> 3) * TL;
    int tw0 = (blockIdx.x & 7) * TL;
    int cb  = blockIdx.y * 32;

    int oy  = tid >> 4, ox = tid & 15;
    int gy2 = th0 * 2 + oy, gx2 = tw0 * 2 + ox;
    int pixhi = (gy2 << 7) + gx2;
    int lh = oy >> 1, lw = ox >> 1;

    float att[25];
#pragma unroll
    for (int o = 0; o < 25; o++)
        att[o] = g_attn[((size_t)(b * 25 + o) << 14) + pixhi];

    const float* xb = x + (size_t)b * C_ * NPIX_LO;
    float* ob = out + (size_t)b * C_ * NPIX_HI + pixhi;

    for (int cg = 0; cg < 4; cg++) {
        int c0 = cb + cg * 8;
        __syncthreads();
        for (int i = tid; i < 8 * HALO * HALO; i += 256) {
            int ch = i / (HALO * HALO);
            int j  = i - ch * (HALO * HALO);
            int jy = j / HALO, jx = j - jy * HALO;
            int gy = th0 - 2 + jy, gx = tw0 - 2 + jx;
            float v = 0.f;
            if (gy >= 0 && gy < 64 && gx >= 0 && gx < 64)
                v = xb[(size_t)(c0 + ch) * NPIX_LO + (gy << 6) + gx];
            x_s[j * 12 + ch] = v;
        }
        __syncthreads();

        ull a2[4];
#pragma unroll
        for (int j = 0; j < 4; j++) a2[j] = 0ull;
#pragma unroll
        for (int o = 0; o < 25; o++) {
            int dy = o / 5, dx = o - 5 * dy;
            const ulonglong2* xp = (const ulonglong2*)
                &x_s[((lh + dy) * HALO + (lw + dx)) * 12];
            ull w = dup2(att[o]);
            ulonglong2 v0 = xp[0], v1 = xp[1];
            FMA2(a2[0], w, v0.x, a2[0]);
            FMA2(a2[1], w, v0.y, a2[1]);
            FMA2(a2[2], w, v1.x, a2[2]);
            FMA2(a2[3], w, v1.y, a2[3]);
        }
#pragma unroll
        for (int j = 0; j < 4; j++) {
            float lo, hi; unpack2(lo, hi, a2[j]);
            ob[(size_t)(c0 + 2*j)     * NPIX_HI] = lo;
            ob[(size_t)(c0 + 2*j + 1) * NPIX_HI] = hi;
        }
    }
}

// ============================================================
extern "C" void kernel_launch(void* const* d_in, const int* in_sizes, int n_in,
                              void* d_out, int out_size)
{
    (void)in_sizes; (void)n_in; (void)out_size;
    const float* y      = (const float*)d_in[0];
    const float* x      = (const float*)d_in[1];
    const float* gn_y_w = (const float*)d_in[2];
    const float* gn_y_b = (const float*)d_in[3];
    const float* gn_x_w = (const float*)d_in[4];
    const float* gn_x_b = (const float*)d_in[5];
    const float* q_w    = (const float*)d_in[6];
    const float* q_b    = (const float*)d_in[7];
    const float* k_w    = (const float*)d_in[8];
    const float* k_b    = (const float*)d_in[9];
    float* out = (float*)d_out;

    stats_partial_kernel<<<640, 256>>>(y, x);
    finalize_kernel<<<33, 256>>>(q_w, k_w, gn_y_w, gn_y_b, gn_x_w, gn_x_b);
    kproj_kernel<<<dim3(NPIX_LO / 32, B_), 256>>>(x, k_b);
    attn_partial_kernel<<<dim3(8, 8, 2 * B_), 256>>>(y, q_b);
    softmax_kernel<<<512, 128>>>();
    sapa_agg_kernel<<<dim3(64, 8, B_), 256>>>(x, out);
}

// round 6
// speedup vs baseline: 1.8865x; 1.4490x over previous
#include <cuda_runtime.h>
#include <cuda_bf16.h>
#include <cstddef>

// SAPA R5: R4 pipeline + 2-pixel/thread register blocking (LDS:FMA2 = 1:4).
#define B_      4
#define C_      256
#define E_      32
#define NPIX_LO 4096
#define NPIX_HI 16384
#define EPSF    1e-5f

typedef unsigned long long ull;

#define FMA2(d, a, b, c) \
    asm("fma.rn.f32x2 %0, %1, %2, %3;" : "=l"(d) : "l"(a), "l"(b), "l"(c))

__device__ __forceinline__ ull pack2(float lo, float hi) {
    ull r; asm("mov.b64 %0, {%1, %2};" : "=l"(r) : "f"(lo), "f"(hi)); return r;
}
__device__ __forceinline__ ull dup2(float v) { return pack2(v, v); }
__device__ __forceinline__ void unpack2(float& lo, float& hi, ull d) {
    asm("mov.b64 {%0, %1}, %2;" : "=f"(lo), "=f"(hi) : "l"(d));
}

// ---------------- device scratch ----------------
__device__ float  g_ps[640];
__device__ float  g_pss[640];
__device__ float2 g_st_y[B_ * C_];
__device__ float2 g_st_x[B_ * C_];
__device__ float  g_qwT[C_ * E_];                  // [c][e]
__device__ float  g_kwT[C_ * E_];                  // [c][e]
__device__ float  g_k[B_ * E_ * NPIX_LO];          // [b][e][pix_lo]
__device__ float  g_logits[2 * B_ * 25 * NPIX_HI]; // [half][b][o][pix_hi]
__device__ float  g_attn[B_ * 25 * NPIX_HI];       // [b][o][pix_hi]

// ============================================================
// Kernel 1: partial sums. blocks [0,512): y chunks; [512,640): x groups.
// ============================================================
__global__ void __launch_bounds__(256)
stats_partial_kernel(const float* __restrict__ y, const float* __restrict__ x)
{
    int bid = blockIdx.x, tid = threadIdx.x;
    const float4* p = (bid < 512)
        ? (const float4*)y + (size_t)bid * 8192
        : (const float4*)x + (size_t)(bid - 512) * 8192;

    float s = 0.f, ss = 0.f;
#pragma unroll 4
    for (int i = tid; i < 8192; i += 256) {
        float4 v = p[i];
        s  += (v.x + v.y) + (v.z + v.w);
        ss += (v.x*v.x + v.y*v.y) + (v.z*v.z + v.w*v.w);
    }
#pragma unroll
    for (int off = 16; off > 0; off >>= 1) {
        s  += __shfl_xor_sync(0xffffffffu, s,  off);
        ss += __shfl_xor_sync(0xffffffffu, ss, off);
    }
    __shared__ float ws[8], wss[8];
    if ((tid & 31) == 0) { ws[tid >> 5] = s; wss[tid >> 5] = ss; }
    __syncthreads();
    if (tid == 0) {
        float ts = 0.f, tss = 0.f;
#pragma unroll
        for (int w = 0; w < 8; w++) { ts += ws[w]; tss += wss[w]; }
        g_ps[bid] = ts; g_pss[bid] = tss;
    }
}

// ============================================================
// Kernel 2: finalize stats -> (scale,shift) tables; transpose weights.
// ============================================================
__global__ void __launch_bounds__(256)
finalize_kernel(const float* __restrict__ qw, const float* __restrict__ kw,
                const float* __restrict__ gyw, const float* __restrict__ gyb,
                const float* __restrict__ gxw, const float* __restrict__ gxb)
{
    int tid = threadIdx.x;
    if (blockIdx.x == 0) {
        __shared__ float mu_s[256], rs_s[256];
        {
            float s, ss, n;
            if (tid < 128) {
                s  = (g_ps[4*tid]  + g_ps[4*tid+1])  + (g_ps[4*tid+2]  + g_ps[4*tid+3]);
                ss = (g_pss[4*tid] + g_pss[4*tid+1]) + (g_pss[4*tid+2] + g_pss[4*tid+3]);
                n = 131072.f;
            } else {
                int g = tid - 128;
                s = g_ps[512 + g]; ss = g_pss[512 + g]; n = 32768.f;
            }
            float mu  = s / n;
            float var = ss / n - mu * mu;
            mu_s[tid] = mu; rs_s[tid] = rsqrtf(var + EPSF);
        }
        __syncthreads();
        for (int i = tid; i < 1024; i += 256) {
            int b = i >> 8, c = i & 255, g = c >> 3;
            {
                float mu = mu_s[b*32 + g], r = rs_s[b*32 + g];
                float sc = r * gyw[c];
                g_st_y[i] = make_float2(sc, gyb[c] - mu * sc);
            }
            {
                float mu = mu_s[128 + b*32 + g], r = rs_s[128 + b*32 + g];
                float sc = r * gxw[c];
                g_st_x[i] = make_float2(sc, gxb[c] - mu * sc);
            }
        }
    } else {
        int i = (blockIdx.x - 1) * 256 + tid;
        int c = i >> 5, e = i & 31;
        g_qwT[i] = qw[e * C_ + c];
        g_kwT[i] = kw[e * C_ + c];
    }
}

// ============================================================
// Kernel 3: k projection (R4). grid (128, 4) x 256.
// ============================================================
__global__ void __launch_bounds__(256)
kproj_kernel(const float* __restrict__ x, const float* __restrict__ k_b)
{
    __shared__ float sm[8448 + 512];
    float* w_s = sm;
    float* r_s = sm;
    float* s_s = sm + 8448;
    float* t_s = sm + 8704;

    int tid = threadIdx.x;
    int b   = blockIdx.y;
    int p   = tid & 31;
    int pix = blockIdx.x * 32 + p;

    for (int i = tid; i < (C_ * E_) / 4; i += 256)
        ((float4*)w_s)[i] = ((const float4*)g_kwT)[i];
    {
        float2 st = g_st_x[b * C_ + tid];
        s_s[tid] = st.x; t_s[tid] = st.y;
    }
    __syncthreads();

    const float* xp = x + (size_t)b * C_ * NPIX_LO + pix;
    const ulonglong2* w2 = (const ulonglong2*)w_s;
    const float4* s4 = (const float4*)s_s;
    const float4* t4 = (const float4*)t_s;

    ull qa2[16];
#pragma unroll
    for (int j = 0; j < 16; j++) qa2[j] = 0ull;

    int cbase = (tid >> 5) * 32;
#pragma unroll 2
    for (int c0 = cbase; c0 < cbase + 32; c0 += 4) {
        float xv0 = xp[(size_t)(c0 + 0) * NPIX_LO];
        float xv1 = xp[(size_t)(c0 + 1) * NPIX_LO];
        float xv2 = xp[(size_t)(c0 + 2) * NPIX_LO];
        float xv3 = xp[(size_t)(c0 + 3) * NPIX_LO];
        float4 sc = s4[c0 >> 2], tc = t4[c0 >> 2];
        ull u0 = dup2(fmaf(xv0, sc.x, tc.x));
        ull u1 = dup2(fmaf(xv1, sc.y, tc.y));
        ull u2 = dup2(fmaf(xv2, sc.z, tc.z));
        ull u3 = dup2(fmaf(xv3, sc.w, tc.w));
#pragma unroll
        for (int j = 0; j < 8; j++) {
            ulonglong2 w0 = w2[(c0 + 0) * 8 + j];
            FMA2(qa2[2*j],   w0.x, u0, qa2[2*j]);
            FMA2(qa2[2*j+1], w0.y, u0, qa2[2*j+1]);
            ulonglong2 w1 = w2[(c0 + 1) * 8 + j];
            FMA2(qa2[2*j],   w1.x, u1, qa2[2*j]);
            FMA2(qa2[2*j+1], w1.y, u1, qa2[2*j+1]);
            ulonglong2 wv = w2[(c0 + 2) * 8 + j];
            FMA2(qa2[2*j],   wv.x, u2, qa2[2*j]);
            FMA2(qa2[2*j+1], wv.y, u2, qa2[2*j+1]);
            ulonglong2 w3 = w2[(c0 + 3) * 8 + j];
            FMA2(qa2[2*j],   w3.x, u3, qa2[2*j]);
            FMA2(qa2[2*j+1], w3.y, u3, qa2[2*j+1]);
        }
    }

    __syncthreads();
#pragma unroll
    for (int j = 0; j < 16; j++) {
        float lo, hi; unpack2(lo, hi, qa2[j]);
        r_s[tid * 33 + 2*j]     = lo;
        r_s[tid * 33 + 2*j + 1] = hi;
    }
    __syncthreads();

    int q4 = tid >> 5;
    int p2 = tid & 31;
    float acc[4];
#pragma unroll
    for (int j = 0; j < 4; j++) acc[j] = __ldg(&k_b[q4 * 4 + j]);
#pragma unroll
    for (int s = 0; s < 8; s++) {
        const float* rp = &r_s[(s * 32 + p2) * 33 + q4 * 4];
#pragma unroll
        for (int j = 0; j < 4; j++) acc[j] += rp[j];
    }
    int pix2 = blockIdx.x * 32 + p2;
#pragma unroll
    for (int j = 0; j < 4; j++)
        g_k[((size_t)(b * E_ + q4 * 4 + j) << 12) + pix2] = acc[j];
}

// ============================================================
// Kernel 4: partial q-proj (c-half) + partial logits -> g_logits.
// grid (4, 8, 8): z = b*2 + half. block 256.
// Thread = 2 horizontally-adjacent hi pixels (share lo pixel/taps).
// Tile: 16 lo-cols x 8 lo-rows (hi 32x16). Halo 20x12 = 240 pts.
// smem floats: w 4096 | sy 128 | ty 128 | k 240*36=8640  (= 51968 B)
// ============================================================
__global__ void __launch_bounds__(256)
attn_partial_kernel(const float* __restrict__ y, const float* __restrict__ q_b)
{
    extern __shared__ float smA[];
    float* w_s  = smA;             // 4096
    float* sy_s = smA + 4096;      // 128
    float* ty_s = smA + 4224;      // 128
    float* k_s  = smA + 4352;      // 8640

    int tid  = threadIdx.x;
    int b    = blockIdx.z >> 1;
    int half = blockIdx.z & 1;
    int th0  = blockIdx.y * 8;     // lo rows
    int tw0  = blockIdx.x * 16;    // lo cols

    for (int i = tid; i < 1024; i += 256)
        ((float4*)w_s)[i] = ((const float4*)g_qwT)[half * 1024 + i];
    if (tid < 128) {
        float2 st = g_st_y[b * C_ + half * 128 + tid];
        sy_s[tid] = st.x; ty_s[tid] = st.y;
    }
    for (int i = tid; i < 7680; i += 256) {
        int e  = i / 240, pt = i - e * 240;
        int jy = pt / 20, jx = pt - jy * 20;
        int gy = th0 - 2 + jy, gx = tw0 - 2 + jx;
        float v = 0.f;
        if (gy >= 0 && gy < 64 && gx >= 0 && gx < 64)
            v = g_k[((size_t)(b * E_ + e) << 12) + (gy << 6) + gx];
        k_s[pt * 36 + e] = v;
    }
    __syncthreads();

    int cp = tid & 15, r = tid >> 4;
    int gy2 = th0 * 2 + r;
    int gx2 = tw0 * 2 + 2 * cp;
    const float* yp = y + ((size_t)b * C_ + half * 128) * NPIX_HI + (gy2 << 7) + gx2;
    const ulonglong2* w2 = (const ulonglong2*)w_s;
    const float4* sy4 = (const float4*)sy_s;
    const float4* ty4 = (const float4*)ty_s;

    ull a0[16], a1[16];
#pragma unroll
    for (int j = 0; j < 16; j++) {
        ull iv = half ? 0ull : pack2(__ldg(&q_b[2*j]), __ldg(&q_b[2*j + 1]));
        a0[j] = iv; a1[j] = iv;
    }

#pragma unroll 2
    for (int c0 = 0; c0 < 128; c0 += 4) {
        float2 yv0 = *(const float2*)(yp + (size_t)(c0 + 0) * NPIX_HI);
        float2 yv1 = *(const float2*)(yp + (size_t)(c0 + 1) * NPIX_HI);
        float2 yv2 = *(const float2*)(yp + (size_t)(c0 + 2) * NPIX_HI);
        float2 yv3 = *(const float2*)(yp + (size_t)(c0 + 3) * NPIX_HI);
        float4 sc = sy4[c0 >> 2], tc = ty4[c0 >> 2];
        ull u00 = dup2(fmaf(yv0.x, sc.x, tc.x)), u01 = dup2(fmaf(yv0.y, sc.x, tc.x));
        ull u10 = dup2(fmaf(yv1.x, sc.y, tc.y)), u11 = dup2(fmaf(yv1.y, sc.y, tc.y));
        ull u20 = dup2(fmaf(yv2.x, sc.z, tc.z)), u21 = dup2(fmaf(yv2.y, sc.z, tc.z));
        ull u30 = dup2(fmaf(yv3.x, sc.w, tc.w)), u31 = dup2(fmaf(yv3.y, sc.w, tc.w));
#pragma unroll
        for (int j = 0; j < 8; j++) {
            ulonglong2 w0 = w2[(c0 + 0) * 8 + j];
            FMA2(a0[2*j],   w0.x, u00, a0[2*j]);   FMA2(a0[2*j+1], w0.y, u00, a0[2*j+1]);
            FMA2(a1[2*j],   w0.x, u01, a1[2*j]);   FMA2(a1[2*j+1], w0.y, u01, a1[2*j+1]);
            ulonglong2 w1 = w2[(c0 + 1) * 8 + j];
            FMA2(a0[2*j],   w1.x, u10, a0[2*j]);   FMA2(a0[2*j+1], w1.y, u10, a0[2*j+1]);
            FMA2(a1[2*j],   w1.x, u11, a1[2*j]);   FMA2(a1[2*j+1], w1.y, u11, a1[2*j+1]);
            ulonglong2 wv = w2[(c0 + 2) * 8 + j];
            FMA2(a0[2*j],   wv.x, u20, a0[2*j]);   FMA2(a0[2*j+1], wv.y, u20, a0[2*j+1]);
            FMA2(a1[2*j],   wv.x, u21, a1[2*j]);   FMA2(a1[2*j+1], wv.y, u21, a1[2*j+1]);
            ulonglong2 w3 = w2[(c0 + 3) * 8 + j];
            FMA2(a0[2*j],   w3.x, u30, a0[2*j]);   FMA2(a0[2*j+1], w3.y, u30, a0[2*j+1]);
            FMA2(a1[2*j],   w3.x, u31, a1[2*j]);   FMA2(a1[2*j+1], w3.y, u31, a1[2*j+1]);
        }
    }

    // partial logits for both pixels (shared taps)
    int lh = r >> 1, lw = cp;
    int pixhi = (gy2 << 7) + gx2;
    float* lg = g_logits + ((size_t)((half * B_ + b) * 25) << 14) + pixhi;
#pragma unroll
    for (int o = 0; o < 25; o++) {
        int dy = o / 5, dx = o - 5 * dy;
        const ulonglong2* kp = (const ulonglong2*)&k_s[((lh + dy) * 20 + lw + dx) * 36];
        ull s0 = 0ull, s1 = 0ull, t0 = 0ull, t1 = 0ull;
#pragma unroll
        for (int j = 0; j < 8; j++) {
            ulonglong2 kv = kp[j];
            FMA2(s0, a0[2*j],   kv.x, s0);  FMA2(s1, a0[2*j+1], kv.y, s1);
            FMA2(t0, a1[2*j],   kv.x, t0);  FMA2(t1, a1[2*j+1], kv.y, t1);
        }
        float p0,p1,p2,p3,q0,q1,q2,q3;
        unpack2(p0, p1, s0); unpack2(p2, p3, s1);
        unpack2(q0, q1, t0); unpack2(q2, q3, t1);
        *(float2*)&lg[(size_t)o << 14] =
            make_float2((p0 + p1) + (p2 + p3), (q0 + q1) + (q2 + q3));
    }
}

// ============================================================
// Kernel 5: sum halves + softmax -> g_attn.  grid 512 x 128.
// ============================================================
__global__ void __launch_bounds__(128)
softmax_kernel()
{
    int i = blockIdx.x * 128 + threadIdx.x;
    int b = i >> 14, pix = i & 16383;
    const float* l0 = g_logits + ((size_t)(b * 25) << 14) + pix;
    const float* l1 = g_logits + ((size_t)((B_ + b) * 25) << 14) + pix;

    float att[25];
    float mx = -1e30f;
#pragma unroll
    for (int o = 0; o < 25; o++) {
        float v = l0[(size_t)o << 14] + l1[(size_t)o << 14];
        att[o] = v;
        mx = fmaxf(mx, v);
    }
    float den = 0.f;
#pragma unroll
    for (int o = 0; o < 25; o++) { float p = __expf(att[o] - mx); att[o] = p; den += p; }
    float inv = 1.f / den;
    float* ap = g_attn + ((size_t)(b * 25) << 14) + pix;
#pragma unroll
    for (int o = 0; o < 25; o++) ap[(size_t)o << 14] = att[o] * inv;
}

// ============================================================
// Kernel 6: aggregation, 2 pixels/thread.  grid (32, 8, 4) x 256.
// Tile: 16 lo-cols x 8 lo-rows (hi 32x16); 32 ch/block in 4 chunks of 8.
// ============================================================
__global__ void __launch_bounds__(256)
agg_kernel(const float* __restrict__ x, float* __restrict__ out)
{
    __shared__ float x_s[240 * 12];

    int tid = threadIdx.x;
    int b   = blockIdx.z;
    int th0 = (blockIdx.x >> 2) * 8;    // lo rows
    int tw0 = (blockIdx.x & 3) * 16;    // lo cols
    int cb  = blockIdx.y * 32;

    int cp = tid & 15, r = tid >> 4;
    int gy2 = th0 * 2 + r, gx2 = tw0 * 2 + 2 * cp;
    int po  = (gy2 << 7) + gx2;
    int lh = r >> 1, lw = cp;

    float att0[25], att1[25];
#pragma unroll
    for (int o = 0; o < 25; o++) {
        float2 a = *(const float2*)&g_attn[((size_t)(b * 25 + o) << 14) + po];
        att0[o] = a.x; att1[o] = a.y;
    }

    const float* xb = x + (size_t)b * C_ * NPIX_LO;
    float* ob = out + (size_t)b * C_ * NPIX_HI + po;

    for (int cg = 0; cg < 4; cg++) {
        int c0 = cb + cg * 8;
        __syncthreads();
        for (int i = tid; i < 1920; i += 256) {
            int ch = i / 240, pt = i - ch * 240;
            int jy = pt / 20, jx = pt - jy * 20;
            int gy = th0 - 2 + jy, gx = tw0 - 2 + jx;
            float v = 0.f;
            if (gy >= 0 && gy < 64 && gx >= 0 && gx < 64)
                v = xb[(size_t)(c0 + ch) * NPIX_LO + (gy << 6) + gx];
            x_s[pt * 12 + ch] = v;
        }
        __syncthreads();

        ull a0[4], a1[4];
#pragma unroll
        for (int j = 0; j < 4; j++) { a0[j] = 0ull; a1[j] = 0ull; }
#pragma unroll
        for (int o = 0; o < 25; o++) {
            int dy = o / 5, dx = o - 5 * dy;
            const ulonglong2* xp = (const ulonglong2*)&x_s[((lh + dy) * 20 + lw + dx) * 12];
            ulonglong2 v0 = xp[0], v1 = xp[1];
            ull w0 = dup2(att0[o]), w1 = dup2(att1[o]);
            FMA2(a0[0], w0, v0.x, a0[0]); FMA2(a0[1], w0, v0.y, a0[1]);
            FMA2(a0[2], w0, v1.x, a0[2]); FMA2(a0[3], w0, v1.y, a0[3]);
            FMA2(a1[0], w1, v0.x, a1[0]); FMA2(a1[1], w1, v0.y, a1[1]);
            FMA2(a1[2], w1, v1.x, a1[2]); FMA2(a1[3], w1, v1.y, a1[3]);
        }
#pragma unroll
        for (int j = 0; j < 4; j++) {
            float l0, h0, l1, h1;
            unpack2(l0, h0, a0[j]);
            unpack2(l1, h1, a1[j]);
            *(ull*)&ob[(size_t)(c0 + 2*j)     * NPIX_HI] = pack2(l0, l1);
            *(ull*)&ob[(size_t)(c0 + 2*j + 1) * NPIX_HI] = pack2(h0, h1);
        }
    }
}

// ============================================================
extern "C" void kernel_launch(void* const* d_in, const int* in_sizes, int n_in,
                              void* d_out, int out_size)
{
    (void)in_sizes; (void)n_in; (void)out_size;
    const float* y      = (const float*)d_in[0];
    const float* x      = (const float*)d_in[1];
    const float* gn_y_w = (const float*)d_in[2];
    const float* gn_y_b = (const float*)d_in[3];
    const float* gn_x_w = (const float*)d_in[4];
    const float* gn_x_b = (const float*)d_in[5];
    const float* q_w    = (const float*)d_in[6];
    const float* q_b    = (const float*)d_in[7];
    const float* k_w    = (const float*)d_in[8];
    const float* k_b    = (const float*)d_in[9];
    float* out = (float*)d_out;

    stats_partial_kernel<<<640, 256>>>(y, x);
    finalize_kernel<<<33, 256>>>(q_w, k_w, gn_y_w, gn_y_b, gn_x_w, gn_x_b);
    kproj_kernel<<<dim3(NPIX_LO / 32, B_), 256>>>(x, k_b);

    static const size_t smemA = (4096 + 128 + 128 + 240 * 36) * sizeof(float); // 51968
    cudaFuncSetAttribute(attn_partial_kernel,
                         cudaFuncAttributeMaxDynamicSharedMemorySize, (int)smemA);
    attn_partial_kernel<<<dim3(4, 8, 2 * B_), 256, smemA>>>(y, q_b);

    softmax_kernel<<<512, 128>>>();
    agg_kernel<<<dim3(32, 8, B_), 256>>>(x, out);
}

// round 7
// speedup vs baseline: 1.9101x; 1.0125x over previous
#include <cuda_runtime.h>
#include <cuda_bf16.h>
#include <cstddef>

// SAPA R7: R5 + deep LDG batching (MLP 8) in attn_partial and kproj.
#define B_      4
#define C_      256
#define E_      32
#define NPIX_LO 4096
#define NPIX_HI 16384
#define EPSF    1e-5f

typedef unsigned long long ull;

#define FMA2(d, a, b, c) \
    asm("fma.rn.f32x2 %0, %1, %2, %3;" : "=l"(d) : "l"(a), "l"(b), "l"(c))

__device__ __forceinline__ ull pack2(float lo, float hi) {
    ull r; asm("mov.b64 %0, {%1, %2};" : "=l"(r) : "f"(lo), "f"(hi)); return r;
}
__device__ __forceinline__ ull dup2(float v) { return pack2(v, v); }
__device__ __forceinline__ void unpack2(float& lo, float& hi, ull d) {
    asm("mov.b64 {%0, %1}, %2;" : "=f"(lo), "=f"(hi) : "l"(d));
}

// ---------------- device scratch ----------------
__device__ float  g_ps[640];
__device__ float  g_pss[640];
__device__ float2 g_st_y[B_ * C_];
__device__ float2 g_st_x[B_ * C_];
__device__ float  g_qwT[C_ * E_];                  // [c][e]
__device__ float  g_kwT[C_ * E_];                  // [c][e]
__device__ float  g_k[B_ * E_ * NPIX_LO];          // [b][e][pix_lo]
__device__ float  g_logits[2 * B_ * 25 * NPIX_HI]; // [half][b][o][pix_hi]
__device__ float  g_attn[B_ * 25 * NPIX_HI];       // [b][o][pix_hi]

// ============================================================
// Kernel 1: partial sums. blocks [0,512): y chunks; [512,640): x groups.
// ============================================================
__global__ void __launch_bounds__(256)
stats_partial_kernel(const float* __restrict__ y, const float* __restrict__ x)
{
    int bid = blockIdx.x, tid = threadIdx.x;
    const float4* p = (bid < 512)
        ? (const float4*)y + (size_t)bid * 8192
        : (const float4*)x + (size_t)(bid - 512) * 8192;

    float s = 0.f, ss = 0.f;
#pragma unroll 4
    for (int i = tid; i < 8192; i += 256) {
        float4 v = p[i];
        s  += (v.x + v.y) + (v.z + v.w);
        ss += (v.x*v.x + v.y*v.y) + (v.z*v.z + v.w*v.w);
    }
#pragma unroll
    for (int off = 16; off > 0; off >>= 1) {
        s  += __shfl_xor_sync(0xffffffffu, s,  off);
        ss += __shfl_xor_sync(0xffffffffu, ss, off);
    }
    __shared__ float ws[8], wss[8];
    if ((tid & 31) == 0) { ws[tid >> 5] = s; wss[tid >> 5] = ss; }
    __syncthreads();
    if (tid == 0) {
        float ts = 0.f, tss = 0.f;
#pragma unroll
        for (int w = 0; w < 8; w++) { ts += ws[w]; tss += wss[w]; }
        g_ps[bid] = ts; g_pss[bid] = tss;
    }
}

// ============================================================
// Kernel 2: finalize stats -> tables; transpose weights.
// ============================================================
__global__ void __launch_bounds__(256)
finalize_kernel(const float* __restrict__ qw, const float* __restrict__ kw,
                const float* __restrict__ gyw, const float* __restrict__ gyb,
                const float* __restrict__ gxw, const float* __restrict__ gxb)
{
    int tid = threadIdx.x;
    if (blockIdx.x == 0) {
        __shared__ float mu_s[256], rs_s[256];
        {
            float s, ss, n;
            if (tid < 128) {
                s  = (g_ps[4*tid]  + g_ps[4*tid+1])  + (g_ps[4*tid+2]  + g_ps[4*tid+3]);
                ss = (g_pss[4*tid] + g_pss[4*tid+1]) + (g_pss[4*tid+2] + g_pss[4*tid+3]);
                n = 131072.f;
            } else {
                int g = tid - 128;
                s = g_ps[512 + g]; ss = g_pss[512 + g]; n = 32768.f;
            }
            float mu  = s / n;
            float var = ss / n - mu * mu;
            mu_s[tid] = mu; rs_s[tid] = rsqrtf(var + EPSF);
        }
        __syncthreads();
        for (int i = tid; i < 1024; i += 256) {
            int b = i >> 8, c = i & 255, g = c >> 3;
            {
                float mu = mu_s[b*32 + g], r = rs_s[b*32 + g];
                float sc = r * gyw[c];
                g_st_y[i] = make_float2(sc, gyb[c] - mu * sc);
            }
            {
                float mu = mu_s[128 + b*32 + g], r = rs_s[128 + b*32 + g];
                float sc = r * gxw[c];
                g_st_x[i] = make_float2(sc, gxb[c] - mu * sc);
            }
        }
    } else {
        int i = (blockIdx.x - 1) * 256 + tid;
        int c = i >> 5, e = i & 31;
        g_qwT[i] = qw[e * C_ + c];
        g_kwT[i] = kw[e * C_ + c];
    }
}

// ============================================================
// Kernel 3: k projection. grid (128, 4) x 256.  MLP-8 loads.
// ============================================================
__global__ void __launch_bounds__(256)
kproj_kernel(const float* __restrict__ x, const float* __restrict__ k_b)
{
    __shared__ float sm[8448 + 512];
    float* w_s = sm;
    float* r_s = sm;
    float* s_s = sm + 8448;
    float* t_s = sm + 8704;

    int tid = threadIdx.x;
    int b   = blockIdx.y;
    int p   = tid & 31;
    int pix = blockIdx.x * 32 + p;

    for (int i = tid; i < (C_ * E_) / 4; i += 256)
        ((float4*)w_s)[i] = ((const float4*)g_kwT)[i];
    {
        float2 st = g_st_x[b * C_ + tid];
        s_s[tid] = st.x; t_s[tid] = st.y;
    }
    __syncthreads();

    const float* xp = x + (size_t)b * C_ * NPIX_LO + pix;
    const ulonglong2* w2 = (const ulonglong2*)w_s;
    const float4* s4 = (const float4*)s_s;
    const float4* t4 = (const float4*)t_s;

    ull qa2[16];
#pragma unroll
    for (int j = 0; j < 16; j++) qa2[j] = 0ull;

    int cbase = (tid >> 5) * 32;
#pragma unroll 2
    for (int c0 = cbase; c0 < cbase + 32; c0 += 8) {
        float xv[8];
#pragma unroll
        for (int j = 0; j < 8; j++)
            xv[j] = xp[(size_t)(c0 + j) * NPIX_LO];
        float4 scA = s4[c0 >> 2], tcA = t4[c0 >> 2];
        float4 scB = s4[(c0 >> 2) + 1], tcB = t4[(c0 >> 2) + 1];
        ull u[8];
        u[0] = dup2(fmaf(xv[0], scA.x, tcA.x));
        u[1] = dup2(fmaf(xv[1], scA.y, tcA.y));
        u[2] = dup2(fmaf(xv[2], scA.z, tcA.z));
        u[3] = dup2(fmaf(xv[3], scA.w, tcA.w));
        u[4] = dup2(fmaf(xv[4], scB.x, tcB.x));
        u[5] = dup2(fmaf(xv[5], scB.y, tcB.y));
        u[6] = dup2(fmaf(xv[6], scB.z, tcB.z));
        u[7] = dup2(fmaf(xv[7], scB.w, tcB.w));
#pragma unroll
        for (int jj = 0; jj < 8; jj++) {
#pragma unroll
            for (int j = 0; j < 8; j++) {
                ulonglong2 wv = w2[(c0 + jj) * 8 + j];
                FMA2(qa2[2*j],   wv.x, u[jj], qa2[2*j]);
                FMA2(qa2[2*j+1], wv.y, u[jj], qa2[2*j+1]);
            }
        }
    }

    __syncthreads();
#pragma unroll
    for (int j = 0; j < 16; j++) {
        float lo, hi; unpack2(lo, hi, qa2[j]);
        r_s[tid * 33 + 2*j]     = lo;
        r_s[tid * 33 + 2*j + 1] = hi;
    }
    __syncthreads();

    int q4 = tid >> 5;
    int p2 = tid & 31;
    float acc[4];
#pragma unroll
    for (int j = 0; j < 4; j++) acc[j] = __ldg(&k_b[q4 * 4 + j]);
#pragma unroll
    for (int s = 0; s < 8; s++) {
        const float* rp = &r_s[(s * 32 + p2) * 33 + q4 * 4];
#pragma unroll
        for (int j = 0; j < 4; j++) acc[j] += rp[j];
    }
    int pix2 = blockIdx.x * 32 + p2;
#pragma unroll
    for (int j = 0; j < 4; j++)
        g_k[((size_t)(b * E_ + q4 * 4 + j) << 12) + pix2] = acc[j];
}

// ============================================================
// Kernel 4: partial q-proj + partial logits. grid (4,8,8) x 256.
// 2 adjacent hi pixels per thread; MLP-8 batched y loads.
// smem floats: w 4096 | sy 128 | ty 128 | k 240*36=8640
// ============================================================
__global__ void __launch_bounds__(256)
attn_partial_kernel(const float* __restrict__ y, const float* __restrict__ q_b)
{
    extern __shared__ float smA[];
    float* w_s  = smA;
    float* sy_s = smA + 4096;
    float* ty_s = smA + 4224;
    float* k_s  = smA + 4352;

    int tid  = threadIdx.x;
    int b    = blockIdx.z >> 1;
    int half = blockIdx.z & 1;
    int th0  = blockIdx.y * 8;
    int tw0  = blockIdx.x * 16;

    for (int i = tid; i < 1024; i += 256)
        ((float4*)w_s)[i] = ((const float4*)g_qwT)[half * 1024 + i];
    if (tid < 128) {
        float2 st = g_st_y[b * C_ + half * 128 + tid];
        sy_s[tid] = st.x; ty_s[tid] = st.y;
    }
    for (int i = tid; i < 7680; i += 256) {
        int e  = i / 240, pt = i - e * 240;
        int jy = pt / 20, jx = pt - jy * 20;
        int gy = th0 - 2 + jy, gx = tw0 - 2 + jx;
        float v = 0.f;
        if (gy >= 0 && gy < 64 && gx >= 0 && gx < 64)
            v = g_k[((size_t)(b * E_ + e) << 12) + (gy << 6) + gx];
        k_s[pt * 36 + e] = v;
    }
    __syncthreads();

    int cp = tid & 15, r = tid >> 4;
    int gy2 = th0 * 2 + r;
    int gx2 = tw0 * 2 + 2 * cp;
    const float* yp = y + ((size_t)b * C_ + half * 128) * NPIX_HI + (gy2 << 7) + gx2;
    const ulonglong2* w2 = (const ulonglong2*)w_s;
    const float4* sy4 = (const float4*)sy_s;
    const float4* ty4 = (const float4*)ty_s;

    ull a0[16], a1[16];
#pragma unroll
    for (int j = 0; j < 16; j++) {
        ull iv = half ? 0ull : pack2(__ldg(&q_b[2*j]), __ldg(&q_b[2*j + 1]));
        a0[j] = iv; a1[j] = iv;
    }

    for (int c0 = 0; c0 < 128; c0 += 8) {
        float2 yv[8];
#pragma unroll
        for (int j = 0; j < 8; j++)
            yv[j] = *(const float2*)(yp + (size_t)(c0 + j) * NPIX_HI);
        float4 scA = sy4[c0 >> 2], tcA = ty4[c0 >> 2];
        float4 scB = sy4[(c0 >> 2) + 1], tcB = ty4[(c0 >> 2) + 1];
        ull u0[8], u1[8];
        u0[0] = dup2(fmaf(yv[0].x, scA.x, tcA.x)); u1[0] = dup2(fmaf(yv[0].y, scA.x, tcA.x));
        u0[1] = dup2(fmaf(yv[1].x, scA.y, tcA.y)); u1[1] = dup2(fmaf(yv[1].y, scA.y, tcA.y));
        u0[2] = dup2(fmaf(yv[2].x, scA.z, tcA.z)); u1[2] = dup2(fmaf(yv[2].y, scA.z, tcA.z));
        u0[3] = dup2(fmaf(yv[3].x, scA.w, tcA.w)); u1[3] = dup2(fmaf(yv[3].y, scA.w, tcA.w));
        u0[4] = dup2(fmaf(yv[4].x, scB.x, tcB.x)); u1[4] = dup2(fmaf(yv[4].y, scB.x, tcB.x));
        u0[5] = dup2(fmaf(yv[5].x, scB.y, tcB.y)); u1[5] = dup2(fmaf(yv[5].y, scB.y, tcB.y));
        u0[6] = dup2(fmaf(yv[6].x, scB.z, tcB.z)); u1[6] = dup2(fmaf(yv[6].y, scB.z, tcB.z));
        u0[7] = dup2(fmaf(yv[7].x, scB.w, tcB.w)); u1[7] = dup2(fmaf(yv[7].y, scB.w, tcB.w));
#pragma unroll
        for (int jj = 0; jj < 8; jj++) {
#pragma unroll
            for (int j = 0; j < 8; j++) {
                ulonglong2 wv = w2[(c0 + jj) * 8 + j];
                FMA2(a0[2*j],   wv.x, u0[jj], a0[2*j]);
                FMA2(a0[2*j+1], wv.y, u0[jj], a0[2*j+1]);
                FMA2(a1[2*j],   wv.x, u1[jj], a1[2*j]);
                FMA2(a1[2*j+1], wv.y, u1[jj], a1[2*j+1]);
            }
        }
    }

    // partial logits for both pixels (shared taps)
    int lh = r >> 1, lw = cp;
    int pixhi = (gy2 << 7) + gx2;
    float* lg = g_logits + ((size_t)((half * B_ + b) * 25) << 14) + pixhi;
#pragma unroll
    for (int o = 0; o < 25; o++) {
        int dy = o / 5, dx = o - 5 * dy;
        const ulonglong2* kp = (const ulonglong2*)&k_s[((lh + dy) * 20 + lw + dx) * 36];
        ull s0 = 0ull, s1 = 0ull, t0 = 0ull, t1 = 0ull;
#pragma unroll
        for (int j = 0; j < 8; j++) {
            ulonglong2 kv = kp[j];
            FMA2(s0, a0[2*j],   kv.x, s0);  FMA2(s1, a0[2*j+1], kv.y, s1);
            FMA2(t0, a1[2*j],   kv.x, t0);  FMA2(t1, a1[2*j+1], kv.y, t1);
        }
        float p0,p1,p2,p3,q0,q1,q2,q3;
        unpack2(p0, p1, s0); unpack2(p2, p3, s1);
        unpack2(q0, q1, t0); unpack2(q2, q3, t1);
        *(float2*)&lg[(size_t)o << 14] =
            make_float2((p0 + p1) + (p2 + p3), (q0 + q1) + (q2 + q3));
    }
}

// ============================================================
// Kernel 5: sum halves + softmax -> g_attn.  grid 512 x 128.
// ============================================================
__global__ void __launch_bounds__(128)
softmax_kernel()
{
    int i = blockIdx.x * 128 + threadIdx.x;
    int b = i >> 14, pix = i & 16383;
    const float* l0 = g_logits + ((size_t)(b * 25) << 14) + pix;
    const float* l1 = g_logits + ((size_t)((B_ + b) * 25) << 14) + pix;

    float att[25];
    float mx = -1e30f;
#pragma unroll
    for (int o = 0; o < 25; o++) {
        float v = l0[(size_t)o << 14] + l1[(size_t)o << 14];
        att[o] = v;
        mx = fmaxf(mx, v);
    }
    float den = 0.f;
#pragma unroll
    for (int o = 0; o < 25; o++) { float p = __expf(att[o] - mx); att[o] = p; den += p; }
    float inv = 1.f / den;
    float* ap = g_attn + ((size_t)(b * 25) << 14) + pix;
#pragma unroll
    for (int o = 0; o < 25; o++) ap[(size_t)o << 14] = att[o] * inv;
}

// ============================================================
// Kernel 6: aggregation, 2 pixels/thread.  grid (32, 8, 4) x 256.
// ============================================================
__global__ void __launch_bounds__(256)
agg_kernel(const float* __restrict__ x, float* __restrict__ out)
{
    __shared__ float x_s[240 * 12];

    int tid = threadIdx.x;
    int b   = blockIdx.z;
    int th0 = (blockIdx.x >> 2) * 8;
    int tw0 = (blockIdx.x & 3) * 16;
    int cb  = blockIdx.y * 32;

    int cp = tid & 15, r = tid >> 4;
    int gy2 = th0 * 2 + r, gx2 = tw0 * 2 + 2 * cp;
    int po  = (gy2 << 7) + gx2;
    int lh = r >> 1, lw = cp;

    float att0[25], att1[25];
#pragma unroll
    for (int o = 0; o < 25; o++) {
        float2 a = *(const float2*)&g_attn[((size_t)(b * 25 + o) << 14) + po];
        att0[o] = a.x; att1[o] = a.y;
    }

    const float* xb = x + (size_t)b * C_ * NPIX_LO;
    float* ob = out + (size_t)b * C_ * NPIX_HI + po;

    for (int cg = 0; cg < 4; cg++) {
        int c0 = cb + cg * 8;
        __syncthreads();
        for (int i = tid; i < 1920; i += 256) {
            int ch = i / 240, pt = i - ch * 240;
            int jy = pt / 20, jx = pt - jy * 20;
            int gy = th0 - 2 + jy, gx = tw0 - 2 + jx;
            float v = 0.f;
            if (gy >= 0 && gy < 64 && gx >= 0 && gx < 64)
                v = xb[(size_t)(c0 + ch) * NPIX_LO + (gy << 6) + gx];
            x_s[pt * 12 + ch] = v;
        }
        __syncthreads();

        ull a0[4], a1[4];
#pragma unroll
        for (int j = 0; j < 4; j++) { a0[j] = 0ull; a1[j] = 0ull; }
#pragma unroll
        for (int o = 0; o < 25; o++) {
            int dy = o / 5, dx = o - 5 * dy;
            const ulonglong2* xp = (const ulonglong2*)&x_s[((lh + dy) * 20 + lw + dx) * 12];
            ulonglong2 v0 = xp[0], v1 = xp[1];
            ull w0 = dup2(att0[o]), w1 = dup2(att1[o]);
            FMA2(a0[0], w0, v0.x, a0[0]); FMA2(a0[1], w0, v0.y, a0[1]);
            FMA2(a0[2], w0, v1.x, a0[2]); FMA2(a0[3], w0, v1.y, a0[3]);
            FMA2(a1[0], w1, v0.x, a1[0]); FMA2(a1[1], w1, v0.y, a1[1]);
            FMA2(a1[2], w1, v1.x, a1[2]); FMA2(a1[3], w1, v1.y, a1[3]);
        }
#pragma unroll
        for (int j = 0; j < 4; j++) {
            float l0, h0, l1, h1;
            unpack2(l0, h0, a0[j]);
            unpack2(l1, h1, a1[j]);
            *(ull*)&ob[(size_t)(c0 + 2*j)     * NPIX_HI] = pack2(l0, l1);
            *(ull*)&ob[(size_t)(c0 + 2*j + 1) * NPIX_HI] = pack2(h0, h1);
        }
    }
}

// ============================================================
extern "C" void kernel_launch(void* const* d_in, const int* in_sizes, int n_in,
                              void* d_out, int out_size)
{
    (void)in_sizes; (void)n_in; (void)out_size;
    const float* y      = (const float*)d_in[0];
    const float* x      = (const float*)d_in[1];
    const float* gn_y_w = (const float*)d_in[2];
    const float* gn_y_b = (const float*)d_in[3];
    const float* gn_x_w = (const float*)d_in[4];
    const float* gn_x_b = (const float*)d_in[5];
    const float* q_w    = (const float*)d_in[6];
    const float* q_b    = (const float*)d_in[7];
    const float* k_w    = (const float*)d_in[8];
    const float* k_b    = (const float*)d_in[9];
    float* out = (float*)d_out;

    stats_partial_kernel<<<640, 256>>>(y, x);
    finalize_kernel<<<33, 256>>>(q_w, k_w, gn_y_w, gn_y_b, gn_x_w, gn_x_b);
    kproj_kernel<<<dim3(NPIX_LO / 32, B_), 256>>>(x, k_b);

    static const size_t smemA = (4096 + 128 + 128 + 240 * 36) * sizeof(float); // 51968
    cudaFuncSetAttribute(attn_partial_kernel,
                         cudaFuncAttributeMaxDynamicSharedMemorySize, (int)smemA);
    attn_partial_kernel<<<dim3(4, 8, 2 * B_), 256, smemA>>>(y, q_b);

    softmax_kernel<<<512, 128>>>();
    agg_kernel<<<dim3(32, 8, B_), 256>>>(x, out);
}